// round 9
// baseline (speedup 1.0000x reference)
#include <cuda_runtime.h>
#include <math.h>

#define Bz 4
#define Nn 4096
#define Hh 128
#define NITERS 8
#define LNEPS 1e-5f

// ---------------- scratch (device globals; no allocation allowed) ----------
__device__ float g_h    [Bz*Nn*Hh];
__device__ float g_c    [Bz*Nn*Hh];
__device__ float g_e    [Bz*Nn*Hh];
__device__ float g_t1   [Bz*Nn*Hh];
__device__ float g_t2   [Bz*Nn*Hh];
__device__ float g_m    [Bz*Nn*Hh];
__device__ float g_mT   [Bz*Nn*Hh];
__device__ float g_msg  [Bz*Nn*Hh];
__device__ float g_gates[Bz*Nn*4*Hh];
__device__ float g_rs   [Bz*Nn];
__device__ float g_i0   [Bz*Hh];
__device__ float g_m0   [Bz*Hh];
__device__ float g_vp   [Bz*8];

__device__ __forceinline__ float sigf(float x){ return 1.f/(1.f+expf(-x)); }

// ---------------- generic NT GEMM: C[M,O] = A[M,K] * W[O,K]^T (+bias)(relu)(accum)
// Column fragment per thread: {o0+tx*4 .. +3} and {o0+64+tx*4 .. +3}
// (16B lane stride -> conflict-free smem reads, N=1)
#define GBM 64
#define GBO 128
#define GBK 16

__global__ __launch_bounds__(128) void gemm_nt(
    const float* __restrict__ Ab, const float* __restrict__ Wb, float* __restrict__ Cb,
    int M, int O, int K,
    size_t sA, size_t sW, size_t sC,
    const float* __restrict__ bias1, const float* __restrict__ bias2,
    int relu, int accum)
{
    const float* A = Ab + (size_t)blockIdx.z * sA;
    const float* W = Wb + (size_t)blockIdx.z * sW;
    float*       C = Cb + (size_t)blockIdx.z * sC;
    const int m0 = blockIdx.x * GBM;
    const int o0 = blockIdx.y * GBO;
    const int tid = threadIdx.x;
    const int ty = tid >> 4;   // 0..7 row group
    const int tx = tid & 15;   // 0..15 col group

    __shared__ __align__(16) float As[2][GBK][GBM];
    __shared__ __align__(16) float Bs[2][GBK][GBO];

    float acc[8][8];
#pragma unroll
    for (int i=0;i<8;i++)
#pragma unroll
        for (int j=0;j<8;j++) acc[i][j]=0.f;

    const int nt = K / GBK;

    // load tile 0
#pragma unroll
    for (int u=0;u<2;u++){
        int idx = tid + u*128; int r = idx>>2, c4 = idx&3;
        float4 v = *(const float4*)(A + (size_t)(m0+r)*K + c4*4);
        As[0][c4*4+0][r]=v.x; As[0][c4*4+1][r]=v.y; As[0][c4*4+2][r]=v.z; As[0][c4*4+3][r]=v.w;
    }
#pragma unroll
    for (int u=0;u<4;u++){
        int idx = tid + u*128; int r = idx>>2, c4 = idx&3;
        float4 v = *(const float4*)(W + (size_t)(o0+r)*K + c4*4);
        Bs[0][c4*4+0][r]=v.x; Bs[0][c4*4+1][r]=v.y; Bs[0][c4*4+2][r]=v.z; Bs[0][c4*4+3][r]=v.w;
    }
    __syncthreads();

    float4 pa[2], pw[4];
    for (int t=0; t<nt; t++){
        const int cur = t & 1;
        if (t+1 < nt){
            const int kt = (t+1)*GBK;
#pragma unroll
            for (int u=0;u<2;u++){
                int idx = tid + u*128; int r = idx>>2, c4 = idx&3;
                pa[u] = *(const float4*)(A + (size_t)(m0+r)*K + kt + c4*4);
            }
#pragma unroll
            for (int u=0;u<4;u++){
                int idx = tid + u*128; int r = idx>>2, c4 = idx&3;
                pw[u] = *(const float4*)(W + (size_t)(o0+r)*K + kt + c4*4);
            }
        }
#pragma unroll
        for (int k=0;k<GBK;k++){
            float4 a0 = *(const float4*)&As[cur][k][ty*8];
            float4 a1 = *(const float4*)&As[cur][k][ty*8+4];
            float4 b0 = *(const float4*)&Bs[cur][k][tx*4];        // 16B lane stride: N=1
            float4 b1 = *(const float4*)&Bs[cur][k][64 + tx*4];   // 16B lane stride: N=1
            float av[8] = {a0.x,a0.y,a0.z,a0.w,a1.x,a1.y,a1.z,a1.w};
            float bv[8] = {b0.x,b0.y,b0.z,b0.w,b1.x,b1.y,b1.z,b1.w};
#pragma unroll
            for (int i=0;i<8;i++)
#pragma unroll
                for (int j=0;j<8;j++)
                    acc[i][j] = fmaf(av[i], bv[j], acc[i][j]);
        }
        if (t+1 < nt){
            const int nb = cur ^ 1;
#pragma unroll
            for (int u=0;u<2;u++){
                int idx = tid + u*128; int r = idx>>2, c4 = idx&3;
                As[nb][c4*4+0][r]=pa[u].x; As[nb][c4*4+1][r]=pa[u].y;
                As[nb][c4*4+2][r]=pa[u].z; As[nb][c4*4+3][r]=pa[u].w;
            }
#pragma unroll
            for (int u=0;u<4;u++){
                int idx = tid + u*128; int r = idx>>2, c4 = idx&3;
                Bs[nb][c4*4+0][r]=pw[u].x; Bs[nb][c4*4+1][r]=pw[u].y;
                Bs[nb][c4*4+2][r]=pw[u].z; Bs[nb][c4*4+3][r]=pw[u].w;
            }
            __syncthreads();
        }
    }

    // epilogue — columns: j<4 -> o0+tx*4+j ; j>=4 -> o0+64+tx*4+(j-4)
    float bb[8];
#pragma unroll
    for (int j=0;j<8;j++) bb[j]=0.f;
    if (bias1){
#pragma unroll
        for (int j=0;j<4;j++){ bb[j] += bias1[o0 + tx*4 + j]; bb[j+4] += bias1[o0 + 64 + tx*4 + j]; }
    }
    if (bias2){
#pragma unroll
        for (int j=0;j<4;j++){ bb[j] += bias2[o0 + tx*4 + j]; bb[j+4] += bias2[o0 + 64 + tx*4 + j]; }
    }
#pragma unroll
    for (int i=0;i<8;i++){
        float* rowp = C + (size_t)(m0 + ty*8 + i)*O + o0;
        float v[8];
#pragma unroll
        for (int j=0;j<8;j++) v[j] = acc[i][j] + bb[j];
        if (accum){
            float4 o0v = *(const float4*)(rowp + tx*4);
            float4 o1v = *(const float4*)(rowp + 64 + tx*4);
            v[0]+=o0v.x; v[1]+=o0v.y; v[2]+=o0v.z; v[3]+=o0v.w;
            v[4]+=o1v.x; v[5]+=o1v.y; v[6]+=o1v.z; v[7]+=o1v.w;
        }
        if (relu){
#pragma unroll
            for (int j=0;j<8;j++) v[j] = fmaxf(v[j], 0.f);
        }
        *(float4*)(rowp + tx*4)      = make_float4(v[0],v[1],v[2],v[3]);
        *(float4*)(rowp + 64 + tx*4) = make_float4(v[4],v[5],v[6],v[7]);
    }
}

// ---------------- fused gate GEMM:
// gates[M,512] = A1[M,128]@W1[512,128]^T + A2[M,128]@W2[512,128]^T + b1 + b2
__global__ __launch_bounds__(128) void gates_gemm(
    const float* __restrict__ A1, const float* __restrict__ W1,
    const float* __restrict__ A2, const float* __restrict__ W2,
    float* __restrict__ C,
    const float* __restrict__ bias1, const float* __restrict__ bias2)
{
    const int M = Bz*Nn;
    const int O = 4*Hh;
    const int K = Hh;
    const int m0 = blockIdx.x * GBM;
    const int o0 = blockIdx.y * GBO;
    const int tid = threadIdx.x;
    const int ty = tid >> 4;
    const int tx = tid & 15;

    __shared__ __align__(16) float As[2][GBK][GBM];
    __shared__ __align__(16) float Bs[2][GBK][GBO];

    float acc[8][8];
#pragma unroll
    for (int i=0;i<8;i++)
#pragma unroll
        for (int j=0;j<8;j++) acc[i][j]=0.f;

    const int nt = K / GBK;   // 8

    for (int ph=0; ph<2; ph++){
        const float* A = ph ? A2 : A1;
        const float* W = ph ? W2 : W1;

        // load tile 0 of this phase into buffer 0
        // (safe: buffer 0's last reader finished before the sync inside tile nt-2)
#pragma unroll
        for (int u=0;u<2;u++){
            int idx = tid + u*128; int r = idx>>2, c4 = idx&3;
            float4 v = *(const float4*)(A + (size_t)(m0+r)*K + c4*4);
            As[0][c4*4+0][r]=v.x; As[0][c4*4+1][r]=v.y; As[0][c4*4+2][r]=v.z; As[0][c4*4+3][r]=v.w;
        }
#pragma unroll
        for (int u=0;u<4;u++){
            int idx = tid + u*128; int r = idx>>2, c4 = idx&3;
            float4 v = *(const float4*)(W + (size_t)(o0+r)*K + c4*4);
            Bs[0][c4*4+0][r]=v.x; Bs[0][c4*4+1][r]=v.y; Bs[0][c4*4+2][r]=v.z; Bs[0][c4*4+3][r]=v.w;
        }
        __syncthreads();

        float4 pa[2], pw[4];
        for (int t=0; t<nt; t++){
            const int cur = t & 1;
            if (t+1 < nt){
                const int kt = (t+1)*GBK;
#pragma unroll
                for (int u=0;u<2;u++){
                    int idx = tid + u*128; int r = idx>>2, c4 = idx&3;
                    pa[u] = *(const float4*)(A + (size_t)(m0+r)*K + kt + c4*4);
                }
#pragma unroll
                for (int u=0;u<4;u++){
                    int idx = tid + u*128; int r = idx>>2, c4 = idx&3;
                    pw[u] = *(const float4*)(W + (size_t)(o0+r)*K + kt + c4*4);
                }
            }
#pragma unroll
            for (int k=0;k<GBK;k++){
                float4 a0 = *(const float4*)&As[cur][k][ty*8];
                float4 a1 = *(const float4*)&As[cur][k][ty*8+4];
                float4 b0 = *(const float4*)&Bs[cur][k][tx*4];
                float4 b1 = *(const float4*)&Bs[cur][k][64 + tx*4];
                float av[8] = {a0.x,a0.y,a0.z,a0.w,a1.x,a1.y,a1.z,a1.w};
                float bv[8] = {b0.x,b0.y,b0.z,b0.w,b1.x,b1.y,b1.z,b1.w};
#pragma unroll
                for (int i=0;i<8;i++)
#pragma unroll
                    for (int j=0;j<8;j++)
                        acc[i][j] = fmaf(av[i], bv[j], acc[i][j]);
            }
            if (t+1 < nt){
                const int nb = cur ^ 1;
#pragma unroll
                for (int u=0;u<2;u++){
                    int idx = tid + u*128; int r = idx>>2, c4 = idx&3;
                    As[nb][c4*4+0][r]=pa[u].x; As[nb][c4*4+1][r]=pa[u].y;
                    As[nb][c4*4+2][r]=pa[u].z; As[nb][c4*4+3][r]=pa[u].w;
                }
#pragma unroll
                for (int u=0;u<4;u++){
                    int idx = tid + u*128; int r = idx>>2, c4 = idx&3;
                    Bs[nb][c4*4+0][r]=pw[u].x; Bs[nb][c4*4+1][r]=pw[u].y;
                    Bs[nb][c4*4+2][r]=pw[u].z; Bs[nb][c4*4+3][r]=pw[u].w;
                }
                __syncthreads();
            }
        }
        // all warps must finish reading the last buffer before phase 1 overwrites
        __syncthreads();
    }

    float bb[8];
#pragma unroll
    for (int j=0;j<4;j++){
        bb[j]   = bias1[o0 + tx*4 + j]      + bias2[o0 + tx*4 + j];
        bb[j+4] = bias1[o0 + 64 + tx*4 + j] + bias2[o0 + 64 + tx*4 + j];
    }
#pragma unroll
    for (int i=0;i<8;i++){
        float* rowp = C + (size_t)(m0 + ty*8 + i)*O + o0;
        *(float4*)(rowp + tx*4)      = make_float4(acc[i][0]+bb[0], acc[i][1]+bb[1], acc[i][2]+bb[2], acc[i][3]+bb[3]);
        *(float4*)(rowp + 64 + tx*4) = make_float4(acc[i][4]+bb[4], acc[i][5]+bb[5], acc[i][6]+bb[6], acc[i][7]+bb[7]);
    }
}

// ---------------- LayerNorm: one 128-thread block per row --------------------
__global__ void ln_kernel(const float* __restrict__ in, float* __restrict__ out,
                          const float* __restrict__ gamma, const float* __restrict__ beta)
{
    size_t row = blockIdx.x;
    int t = threadIdx.x;
    float v = in[row*Hh + t];
    float s = v;
#pragma unroll
    for (int o=16;o>0;o>>=1) s += __shfl_xor_sync(0xffffffffu, s, o);
    __shared__ float sm[4], sv[4];
    int w = t>>5, l = t&31;
    if (l==0) sm[w] = s;
    __syncthreads();
    float mu = (sm[0]+sm[1]+sm[2]+sm[3]) * (1.0f/Hh);
    float xc = v - mu;
    float q = xc*xc;
#pragma unroll
    for (int o=16;o>0;o>>=1) q += __shfl_xor_sync(0xffffffffu, q, o);
    if (l==0) sv[w] = q;
    __syncthreads();
    float var = (sv[0]+sv[1]+sv[2]+sv[3]) * (1.0f/Hh);
    out[row*Hh + t] = xc * rsqrtf(var + LNEPS) * gamma[t] + beta[t];
}

// ---------------- fused LSTM pointwise + LayerNorm: one block per row --------
__global__ void lstm_ln(const float* __restrict__ gates,
                        float* __restrict__ c, float* __restrict__ h,
                        float* __restrict__ e,
                        const float* __restrict__ gamma, const float* __restrict__ beta)
{
    size_t row = blockIdx.x;
    int t = threadIdx.x;
    const float* g = gates + row*(4*Hh);
    size_t idx = row*Hh + t;

    float iv = sigf(g[t]);
    float fv = sigf(g[Hh + t]);
    float gv = tanhf(g[2*Hh + t]);
    float ov = sigf(g[3*Hh + t]);
    float cn = fv*c[idx] + iv*gv;
    c[idx] = cn;
    float hv = ov*tanhf(cn);
    h[idx] = hv;

    // LayerNorm over the 128 h values of this row
    float s = hv;
#pragma unroll
    for (int o=16;o>0;o>>=1) s += __shfl_xor_sync(0xffffffffu, s, o);
    __shared__ float sm[4], sv[4];
    int w = t>>5, l = t&31;
    if (l==0) sm[w] = s;
    __syncthreads();
    float mu = (sm[0]+sm[1]+sm[2]+sm[3]) * (1.0f/Hh);
    float xc = hv - mu;
    float q = xc*xc;
#pragma unroll
    for (int o=16;o>0;o>>=1) q += __shfl_xor_sync(0xffffffffu, q, o);
    if (l==0) sv[w] = q;
    __syncthreads();
    float var = (sv[0]+sv[1]+sv[2]+sv[3]) * (1.0f/Hh);
    e[idx] = xc * rsqrtf(var + LNEPS) * gamma[t] + beta[t];
}

// ---------------- init MLP (2 -> H -> H -> H), one block per batch -----------
__global__ void init_mlp(const float* __restrict__ kk, const float* __restrict__ nn,
    const float* __restrict__ w1, const float* __restrict__ b1,
    const float* __restrict__ w2, const float* __restrict__ b2,
    const float* __restrict__ w3, const float* __restrict__ b3,
    float* __restrict__ out)
{
    int b = blockIdx.x, t = threadIdx.x;
    __shared__ float s0[Hh], s1[Hh];
    float a = w1[t*2+0]*kk[b] + w1[t*2+1]*nn[b] + b1[t];
    s0[t] = fmaxf(a, 0.f);
    __syncthreads();
    a = b2[t];
    for (int q=0;q<Hh;q++) a = fmaf(w2[t*Hh+q], s0[q], a);
    s1[t] = fmaxf(a, 0.f);
    __syncthreads();
    a = b3[t];
    for (int q=0;q<Hh;q++) a = fmaf(w3[t*Hh+q], s1[q], a);
    out[b*Hh + t] = a;
}

// ---------------- msg MLP on one row per batch (iteration-0 fast path) -------
__global__ void m0_mlp(const float* __restrict__ embed,
    const float* __restrict__ w1, const float* __restrict__ b1,
    const float* __restrict__ w2, const float* __restrict__ b2,
    const float* __restrict__ w3, const float* __restrict__ b3,
    float* __restrict__ out)
{
    int b = blockIdx.x, t = threadIdx.x;
    __shared__ float s0[Hh], s1[Hh];
    s0[t] = embed[(size_t)b*Nn*Hh + t];   // row 0 of batch b (all rows identical)
    __syncthreads();
    float a = b1[t];
    for (int q=0;q<Hh;q++) a = fmaf(w1[t*Hh+q], s0[q], a);
    s1[t] = fmaxf(a, 0.f);
    __syncthreads();
    a = b2[t];
    for (int q=0;q<Hh;q++) a = fmaf(w2[t*Hh+q], s1[q], a);
    __syncthreads();
    s0[t] = fmaxf(a, 0.f);
    __syncthreads();
    a = b3[t];
    for (int q=0;q<Hh;q++) a = fmaf(w3[t*Hh+q], s0[q], a);
    out[b*Hh + t] = a;
}

// ---------------- row sums of x (once) ---------------------------------------
__global__ void rowsum_kernel(const float* __restrict__ x, float* __restrict__ rs)
{
    size_t row = blockIdx.x;
    const float4* p = (const float4*)(x + row*(size_t)Nn);
    float s = 0.f;
    for (int j=threadIdx.x; j<Nn/4; j+=128){
        float4 v = p[j];
        s += (v.x+v.y)+(v.z+v.w);
    }
#pragma unroll
    for (int o=16;o>0;o>>=1) s += __shfl_xor_sync(0xffffffffu, s, o);
    __shared__ float sm[4];
    int w = threadIdx.x>>5, l = threadIdx.x&31;
    if (l==0) sm[w] = s;
    __syncthreads();
    if (threadIdx.x==0) rs[row] = (sm[0]+sm[1])+(sm[2]+sm[3]);
}

// ---------------- broadcast init0 into h, zero c -----------------------------
__global__ void bcast_init(const float* __restrict__ i0, float* __restrict__ h, float* __restrict__ c)
{
    size_t idx = (size_t)blockIdx.x*blockDim.x + threadIdx.x;
    int b  = (int)(idx / ((size_t)Nn*Hh));
    int hh = (int)(idx % Hh);
    h[idx] = i0[b*Hh + hh];
    c[idx] = 0.f;
}

// ---------------- iteration-0 msg = rowsum outer m0 --------------------------
__global__ void outer_msg(const float* __restrict__ rs, const float* __restrict__ m0,
                          float* __restrict__ msg)
{
    size_t idx = (size_t)blockIdx.x*blockDim.x + threadIdx.x;
    int b  = (int)(idx / ((size_t)Nn*Hh));
    size_t row = idx / Hh;
    int hh = (int)(idx % Hh);
    msg[idx] = rs[row] * m0[b*Hh + hh];
}

// ---------------- transpose m [B,N,H] -> mT [B,H,N] --------------------------
__global__ void transpose_k(const float* __restrict__ in, float* __restrict__ out)
{
    __shared__ float tile[32][33];
    int b  = blockIdx.z;
    int j0 = blockIdx.x*32;
    int h0 = blockIdx.y*32;
    int tx = threadIdx.x, ty = threadIdx.y;
#pragma unroll
    for (int i=0;i<32;i+=8)
        tile[ty+i][tx] = in[((size_t)b*Nn + j0+ty+i)*Hh + h0+tx];
    __syncthreads();
#pragma unroll
    for (int i=0;i<32;i+=8)
        out[((size_t)b*Hh + h0+ty+i)*Nn + j0+tx] = tile[tx][ty+i];
}

// ---------------- vote layer-3 + masked partial sums -------------------------
__global__ void vote_part(const float* __restrict__ v2, const float* __restrict__ w3,
                          const float* __restrict__ b3v, const float* __restrict__ mask,
                          float* __restrict__ part)
{
    int b = blockIdx.y;
    int blk = blockIdx.x;          // 0..7
    int tid = threadIdx.x;         // 256
    int w = tid>>5, l = tid&31;
    __shared__ float sw[Hh];
    if (tid < Hh) sw[tid] = w3[tid];
    __syncthreads();
    float s = 0.f;
    for (int i = blk*8 + w; i < Nn; i += 64){
        const float* rp = v2 + ((size_t)b*Nn + i)*Hh;
        float d = 0.f;
#pragma unroll
        for (int q=0;q<4;q++) d = fmaf(rp[l + 32*q], sw[l + 32*q], d);
#pragma unroll
        for (int o=16;o>0;o>>=1) d += __shfl_xor_sync(0xffffffffu, d, o);
        s += (d + b3v[0]) * mask[(size_t)b*Nn + i];
    }
    __shared__ float wsum[8];
    if (l==0) wsum[w] = s;
    __syncthreads();
    if (tid==0){
        float t = 0.f;
        for (int q=0;q<8;q++) t += wsum[q];
        part[b*8 + blk] = t;
    }
}

__global__ void vote_final(const float* __restrict__ part, float* __restrict__ out)
{
    int b = threadIdx.x;
    if (b < Bz){
        float s = 0.f;
        for (int q=0;q<8;q++) s += part[b*8+q];
        out[b] = 1.f/(1.f+expf(-s));
    }
}

// =============================================================================
extern "C" void kernel_launch(void* const* d_in, const int* in_sizes, int n_in,
                              void* d_out, int out_size)
{
    const float* x    = (const float*)d_in[0];
    const float* kv   = (const float*)d_in[1];
    const float* nv   = (const float*)d_in[2];
    const float* mask = (const float*)d_in[3];
    const float* iw1  = (const float*)d_in[4];
    const float* ib1  = (const float*)d_in[5];
    const float* iw2  = (const float*)d_in[6];
    const float* ib2  = (const float*)d_in[7];
    const float* iw3  = (const float*)d_in[8];
    const float* ib3  = (const float*)d_in[9];
    const float* mw1  = (const float*)d_in[10];
    const float* mb1  = (const float*)d_in[11];
    const float* mw2  = (const float*)d_in[12];
    const float* mb2  = (const float*)d_in[13];
    const float* mw3  = (const float*)d_in[14];
    const float* mb3  = (const float*)d_in[15];
    const float* wih  = (const float*)d_in[16];
    const float* whh  = (const float*)d_in[17];
    const float* bih  = (const float*)d_in[18];
    const float* bhh  = (const float*)d_in[19];
    const float* lng  = (const float*)d_in[20];
    const float* lnb  = (const float*)d_in[21];
    const float* vw1  = (const float*)d_in[22];
    const float* vb1  = (const float*)d_in[23];
    const float* vw2  = (const float*)d_in[24];
    const float* vb2  = (const float*)d_in[25];
    const float* vw3  = (const float*)d_in[26];
    const float* vb3  = (const float*)d_in[27];
    float* out = (float*)d_out;

    float *p_h,*p_c,*p_e,*p_t1,*p_t2,*p_m,*p_mT,*p_msg,*p_g,*p_rs,*p_i0,*p_m0,*p_vp;
    cudaGetSymbolAddress((void**)&p_h,   g_h);
    cudaGetSymbolAddress((void**)&p_c,   g_c);
    cudaGetSymbolAddress((void**)&p_e,   g_e);
    cudaGetSymbolAddress((void**)&p_t1,  g_t1);
    cudaGetSymbolAddress((void**)&p_t2,  g_t2);
    cudaGetSymbolAddress((void**)&p_m,   g_m);
    cudaGetSymbolAddress((void**)&p_mT,  g_mT);
    cudaGetSymbolAddress((void**)&p_msg, g_msg);
    cudaGetSymbolAddress((void**)&p_g,   g_gates);
    cudaGetSymbolAddress((void**)&p_rs,  g_rs);
    cudaGetSymbolAddress((void**)&p_i0,  g_i0);
    cudaGetSymbolAddress((void**)&p_m0,  g_m0);
    cudaGetSymbolAddress((void**)&p_vp,  g_vp);

    const int BN = Bz*Nn;                 // 16384 rows
    const int ELEM_BLOCKS = (BN*Hh)/256;  // 8192

    // ---- init ----
    init_mlp<<<Bz, Hh>>>(kv, nv, iw1, ib1, iw2, ib2, iw3, ib3, p_i0);
    rowsum_kernel<<<BN, 128>>>(x, p_rs);
    bcast_init<<<ELEM_BLOCKS, 256>>>(p_i0, p_h, p_c);
    ln_kernel<<<BN, Hh>>>(p_h, p_e, lng, lnb);

    // ---- iteration 0 (h broadcast => msg = rowsum x m0, outer product) ----
    m0_mlp<<<Bz, Hh>>>(p_e, mw1, mb1, mw2, mb2, mw3, mb3, p_m0);
    outer_msg<<<ELEM_BLOCKS, 256>>>(p_rs, p_m0, p_msg);
    gates_gemm<<<dim3(BN/GBM, (4*Hh)/GBO), 128>>>(p_msg, wih, p_h, whh, p_g, bih, bhh);
    lstm_ln<<<BN, Hh>>>(p_g, p_c, p_h, p_e, lng, lnb);

    // ---- iterations 1..7 ----
    for (int it = 1; it < NITERS; it++){
        gemm_nt<<<dim3(BN/GBM, 1, 1), 128>>>(p_e,  mw1, p_t1, BN, Hh, Hh, 0,0,0, mb1, nullptr, 1, 0);
        gemm_nt<<<dim3(BN/GBM, 1, 1), 128>>>(p_t1, mw2, p_t2, BN, Hh, Hh, 0,0,0, mb2, nullptr, 1, 0);
        gemm_nt<<<dim3(BN/GBM, 1, 1), 128>>>(p_t2, mw3, p_m,  BN, Hh, Hh, 0,0,0, mb3, nullptr, 0, 0);
        transpose_k<<<dim3(Nn/32, Hh/32, Bz), dim3(32, 8)>>>(p_m, p_mT);
        // msg[b] = x[b] (NxN) @ m[b] (NxH)  via NT with mT
        gemm_nt<<<dim3(Nn/GBM, 1, Bz), 128>>>(x, p_mT, p_msg, Nn, Hh, Nn,
            (size_t)Nn*Nn, (size_t)Hh*Nn, (size_t)Nn*Hh, nullptr, nullptr, 0, 0);
        gates_gemm<<<dim3(BN/GBM, (4*Hh)/GBO), 128>>>(p_msg, wih, p_h, whh, p_g, bih, bhh);
        lstm_ln<<<BN, Hh>>>(p_g, p_c, p_h, p_e, lng, lnb);
    }

    // ---- vote ----
    gemm_nt<<<dim3(BN/GBM, 1, 1), 128>>>(p_e,  vw1, p_t1, BN, Hh, Hh, 0,0,0, vb1, nullptr, 1, 0);
    gemm_nt<<<dim3(BN/GBM, 1, 1), 128>>>(p_t1, vw2, p_t2, BN, Hh, Hh, 0,0,0, vb2, nullptr, 1, 0);
    vote_part<<<dim3(8, Bz), 256>>>(p_t2, vw3, vb3, mask, p_vp);
    vote_final<<<1, 32>>>(p_vp, out);
}

// round 16
// speedup vs baseline: 2.0058x; 2.0058x over previous
#include <cuda_runtime.h>
#include <cuda_bf16.h>
#include <math.h>
#include <stdint.h>

#define Bz 4
#define Nn 4096
#define Hh 128
#define NITERS 8
#define LNEPS 1e-5f

// ---------------- scratch (device globals; no allocation allowed) ----------
__device__ float g_h    [Bz*Nn*Hh];
__device__ float g_c    [Bz*Nn*Hh];
__device__ float g_e    [Bz*Nn*Hh];
__device__ float g_t1   [Bz*Nn*Hh];
__device__ float g_t2   [Bz*Nn*Hh];
__device__ float g_m    [Bz*Nn*Hh];
__device__ float g_msg  [Bz*Nn*Hh];
__device__ float g_gates[Bz*Nn*4*Hh];
__device__ float g_rs   [Bz*Nn];
__device__ float g_i0   [Bz*Hh];
__device__ float g_m0   [Bz*Hh];
__device__ float g_vp   [Bz*8];
// bf16 split-precision operands for tensor-core aggregation
__device__ __nv_bfloat16 g_xh [Bz*Nn*Nn];
__device__ __nv_bfloat16 g_xl [Bz*Nn*Nn];
__device__ __nv_bfloat16 g_mTh[Bz*Hh*Nn];
__device__ __nv_bfloat16 g_mTl[Bz*Hh*Nn];

__device__ __forceinline__ float sigf(float x){ return 1.f/(1.f+expf(-x)); }

__device__ __forceinline__ uint32_t smem_to_u32(const void* smem_ptr) {
    uint32_t addr;
    asm("{ .reg .u64 tmp; cvta.to.shared.u64 tmp, %1; cvt.u32.u64 %0, tmp; }"
        : "=r"(addr) : "l"(smem_ptr));
    return addr;
}

#define CP_ASYNC16(daddr, gptr) \
    asm volatile("cp.async.cg.shared.global [%0], [%1], 16;" \
        :: "r"(daddr), "l"(gptr) : "memory")
#define CP_COMMIT()  asm volatile("cp.async.commit_group;" ::: "memory")
#define CP_WAIT0()   asm volatile("cp.async.wait_group 0;" ::: "memory")

// mma.sync m16n8k16 bf16 (row.col), fp32 accumulate — sm_80+ baseline PTX
#define MMA_BF16(d, a, b0v, b1v) \
    asm volatile("mma.sync.aligned.m16n8k16.row.col.f32.bf16.bf16.f32 " \
        "{%0,%1,%2,%3}, {%4,%5,%6,%7}, {%8,%9}, {%0,%1,%2,%3};" \
        : "+f"((d)[0]), "+f"((d)[1]), "+f"((d)[2]), "+f"((d)[3]) \
        : "r"((a)[0]), "r"((a)[1]), "r"((a)[2]), "r"((a)[3]), "r"(b0v), "r"(b1v))

// ================= tensor-core aggregation (mma.sync path) ===================
// msg[b, i0:i0+128, :] = x[b, i0:i0+128, :] @ m[b]  via hi/lo bf16 split.
// smem tiles: Ah/Al [128 rows x 64 k] bf16 (row pad to 72), Bh/Bl [128 n x 64 k].
#define SP    72                         // padded row stride (bf16 elems), 144 B
#define ATILE (128*SP*2)                 // 18432 B per array
#define ABUF  (4*ATILE)                  // 73728 B per buffer
#define AGG_SMEM (2*ABUF)                // 147456 B, double-buffered

__global__ __launch_bounds__(256) void agg_mma(
    const __nv_bfloat16* __restrict__ xh, const __nv_bfloat16* __restrict__ xl,
    const __nv_bfloat16* __restrict__ mTh, const __nv_bfloat16* __restrict__ mTl,
    float* __restrict__ msg)
{
    extern __shared__ char sm[];
    const int tid = threadIdx.x;
    const int wid = tid >> 5, lid = tid & 31;
    const int b  = blockIdx.z;
    const int i0 = blockIdx.x * 128;
    const int g  = lid >> 2, tg = lid & 3;
    const int wm = (wid >> 1) * 32;      // warp row base 0/32/64/96
    const int wn = (wid & 1) * 64;       // warp col base 0/64

    const __nv_bfloat16* pxh = xh  + (size_t)b*Nn*Nn;
    const __nv_bfloat16* pxl = xl  + (size_t)b*Nn*Nn;
    const __nv_bfloat16* pbh = mTh + (size_t)b*Hh*Nn;
    const __nv_bfloat16* pbl = mTl + (size_t)b*Hh*Nn;

    float acc[2][8][4];
#pragma unroll
    for (int mt=0; mt<2; mt++)
#pragma unroll
        for (int nt=0; nt<8; nt++)
#pragma unroll
            for (int q=0; q<4; q++) acc[mt][nt][q] = 0.f;

    // ---- async loader: one 64-k chunk (4 arrays x 128 rows x 128 B) ----
    auto issue_loads = [&](int buf, int ic){
        char* dstb = sm + buf*ABUF;
#pragma unroll
        for (int j = 0; j < 16; j++){
            int idx = tid + j*256;               // 0..4095
            int arr = idx >> 10;                 // 0..3 (warp-uniform per j)
            int rem = idx & 1023;
            int r = rem >> 3, q = rem & 7;       // row 0..127, 16B chunk 0..7
            const __nv_bfloat16* gp;
            if (arr == 0)      gp = pxh + (size_t)(i0+r)*Nn + ic*64 + q*8;
            else if (arr == 1) gp = pxl + (size_t)(i0+r)*Nn + ic*64 + q*8;
            else if (arr == 2) gp = pbh + (size_t)r*Nn + ic*64 + q*8;
            else               gp = pbl + (size_t)r*Nn + ic*64 + q*8;
            uint32_t daddr = smem_to_u32(dstb + arr*ATILE + (r*SP + q*8)*2);
            CP_ASYNC16(daddr, gp);
        }
        CP_COMMIT();
    };

    // ---- compute one 64-k chunk ----
    auto compute = [&](int buf){
        const char* basep = sm + buf*ABUF;
        const __nv_bfloat16* Ah = (const __nv_bfloat16*)(basep);
        const __nv_bfloat16* Al = (const __nv_bfloat16*)(basep + ATILE);
        const __nv_bfloat16* Bh = (const __nv_bfloat16*)(basep + 2*ATILE);
        const __nv_bfloat16* Bl = (const __nv_bfloat16*)(basep + 3*ATILE);
#pragma unroll
        for (int ks = 0; ks < 4; ks++){
            const int k0 = ks*16;
            uint32_t ah[2][4], al[2][4];
#pragma unroll
            for (int mt=0; mt<2; mt++){
                int rb = wm + mt*16;
                ah[mt][0] = *(const uint32_t*)&Ah[(rb+g  )*SP + k0 + tg*2];
                ah[mt][1] = *(const uint32_t*)&Ah[(rb+g+8)*SP + k0 + tg*2];
                ah[mt][2] = *(const uint32_t*)&Ah[(rb+g  )*SP + k0 + tg*2 + 8];
                ah[mt][3] = *(const uint32_t*)&Ah[(rb+g+8)*SP + k0 + tg*2 + 8];
                al[mt][0] = *(const uint32_t*)&Al[(rb+g  )*SP + k0 + tg*2];
                al[mt][1] = *(const uint32_t*)&Al[(rb+g+8)*SP + k0 + tg*2];
                al[mt][2] = *(const uint32_t*)&Al[(rb+g  )*SP + k0 + tg*2 + 8];
                al[mt][3] = *(const uint32_t*)&Al[(rb+g+8)*SP + k0 + tg*2 + 8];
            }
#pragma unroll
            for (int nt=0; nt<8; nt++){
                int cb = wn + nt*8;
                uint32_t bh0 = *(const uint32_t*)&Bh[(cb+g)*SP + k0 + tg*2];
                uint32_t bh1 = *(const uint32_t*)&Bh[(cb+g)*SP + k0 + tg*2 + 8];
                uint32_t bl0 = *(const uint32_t*)&Bl[(cb+g)*SP + k0 + tg*2];
                uint32_t bl1 = *(const uint32_t*)&Bl[(cb+g)*SP + k0 + tg*2 + 8];
#pragma unroll
                for (int mt=0; mt<2; mt++){
                    MMA_BF16(acc[mt][nt], ah[mt], bh0, bh1);   // hi*hi
                    MMA_BF16(acc[mt][nt], ah[mt], bl0, bl1);   // hi*lo
                    MMA_BF16(acc[mt][nt], al[mt], bh0, bh1);   // lo*hi
                }
            }
        }
    };

    issue_loads(0, 0);
    CP_WAIT0();
    __syncthreads();

    const int NCH = Nn/64;   // 64 chunks
    for (int ic = 0; ic < NCH; ic++){
        const int cur = ic & 1;
        if (ic + 1 < NCH) issue_loads(cur ^ 1, ic + 1);
        compute(cur);
        if (ic + 1 < NCH){
            CP_WAIT0();
            __syncthreads();
        }
    }

    // ---- store (fragment layout: c0,c1 row g cols 2tg,2tg+1; c2,c3 row g+8) --
#pragma unroll
    for (int mt=0; mt<2; mt++){
#pragma unroll
        for (int nt=0; nt<8; nt++){
            int row = i0 + wm + mt*16;
            int col = wn + nt*8 + tg*2;
            float2 lo; lo.x = acc[mt][nt][0]; lo.y = acc[mt][nt][1];
            float2 hi; hi.x = acc[mt][nt][2]; hi.y = acc[mt][nt][3];
            *(float2*)&msg[((size_t)b*Nn + row + g    )*Hh + col] = lo;
            *(float2*)&msg[((size_t)b*Nn + row + g + 8)*Hh + col] = hi;
        }
    }
}

// ---------------- x -> (x_hi, x_lo) bf16 split (once) ------------------------
__global__ void conv_x(const float4* __restrict__ x,
                       __nv_bfloat16* __restrict__ xh, __nv_bfloat16* __restrict__ xl)
{
    size_t i = (size_t)blockIdx.x*256 + threadIdx.x;
    float4 v = x[i];
    __nv_bfloat16 h0 = __float2bfloat16(v.x), h1 = __float2bfloat16(v.y);
    __nv_bfloat16 h2 = __float2bfloat16(v.z), h3 = __float2bfloat16(v.w);
    __nv_bfloat16 l0 = __float2bfloat16(v.x - __bfloat162float(h0));
    __nv_bfloat16 l1 = __float2bfloat16(v.y - __bfloat162float(h1));
    __nv_bfloat16 l2 = __float2bfloat16(v.z - __bfloat162float(h2));
    __nv_bfloat16 l3 = __float2bfloat16(v.w - __bfloat162float(h3));
    __nv_bfloat162* ph = (__nv_bfloat162*)xh + 2*i;
    __nv_bfloat162* pl = (__nv_bfloat162*)xl + 2*i;
    __nv_bfloat162 a; a.x=h0; a.y=h1; ph[0]=a; a.x=h2; a.y=h3; ph[1]=a;
    __nv_bfloat162 c; c.x=l0; c.y=l1; pl[0]=c; c.x=l2; c.y=l3; pl[1]=c;
}

// ---------------- transpose m [B,N,H] -> mT hi/lo bf16 [B,H,N] ---------------
__global__ void transpose_conv(const float* __restrict__ in,
                               __nv_bfloat16* __restrict__ oh, __nv_bfloat16* __restrict__ ol)
{
    __shared__ float tile[32][33];
    int b  = blockIdx.z;
    int j0 = blockIdx.x*32;
    int h0 = blockIdx.y*32;
    int tx = threadIdx.x, ty = threadIdx.y;
#pragma unroll
    for (int i=0;i<32;i+=8)
        tile[ty+i][tx] = in[((size_t)b*Nn + j0+ty+i)*Hh + h0+tx];
    __syncthreads();
#pragma unroll
    for (int i=0;i<32;i+=8){
        float f = tile[tx][ty+i];
        __nv_bfloat16 h = __float2bfloat16(f);
        __nv_bfloat16 l = __float2bfloat16(f - __bfloat162float(h));
        size_t o = ((size_t)b*Hh + h0+ty+i)*Nn + j0+tx;
        oh[o] = h; ol[o] = l;
    }
}

// ---------------- generic NT GEMM (conflict-free variant from R6) ------------
#define GBM 64
#define GBO 128
#define GBK 16

__global__ __launch_bounds__(128) void gemm_nt(
    const float* __restrict__ Ab, const float* __restrict__ Wb, float* __restrict__ Cb,
    int M, int O, int K,
    size_t sA, size_t sW, size_t sC,
    const float* __restrict__ bias1, const float* __restrict__ bias2,
    int relu, int accum)
{
    const float* A = Ab + (size_t)blockIdx.z * sA;
    const float* W = Wb + (size_t)blockIdx.z * sW;
    float*       C = Cb + (size_t)blockIdx.z * sC;
    const int m0 = blockIdx.x * GBM;
    const int o0 = blockIdx.y * GBO;
    const int tid = threadIdx.x;
    const int ty = tid >> 4;
    const int tx = tid & 15;

    __shared__ __align__(16) float As[2][GBK][GBM];
    __shared__ __align__(16) float Bs[2][GBK][GBO];

    float acc[8][8];
#pragma unroll
    for (int i=0;i<8;i++)
#pragma unroll
        for (int j=0;j<8;j++) acc[i][j]=0.f;

    const int nt = K / GBK;

#pragma unroll
    for (int u=0;u<2;u++){
        int idx = tid + u*128; int r = idx>>2, c4 = idx&3;
        float4 v = *(const float4*)(A + (size_t)(m0+r)*K + c4*4);
        As[0][c4*4+0][r]=v.x; As[0][c4*4+1][r]=v.y; As[0][c4*4+2][r]=v.z; As[0][c4*4+3][r]=v.w;
    }
#pragma unroll
    for (int u=0;u<4;u++){
        int idx = tid + u*128; int r = idx>>2, c4 = idx&3;
        float4 v = *(const float4*)(W + (size_t)(o0+r)*K + c4*4);
        Bs[0][c4*4+0][r]=v.x; Bs[0][c4*4+1][r]=v.y; Bs[0][c4*4+2][r]=v.z; Bs[0][c4*4+3][r]=v.w;
    }
    __syncthreads();

    float4 pa[2], pw[4];
    for (int t=0; t<nt; t++){
        const int cur = t & 1;
        if (t+1 < nt){
            const int kt = (t+1)*GBK;
#pragma unroll
            for (int u=0;u<2;u++){
                int idx = tid + u*128; int r = idx>>2, c4 = idx&3;
                pa[u] = *(const float4*)(A + (size_t)(m0+r)*K + kt + c4*4);
            }
#pragma unroll
            for (int u=0;u<4;u++){
                int idx = tid + u*128; int r = idx>>2, c4 = idx&3;
                pw[u] = *(const float4*)(W + (size_t)(o0+r)*K + kt + c4*4);
            }
        }
#pragma unroll
        for (int k=0;k<GBK;k++){
            float4 a0 = *(const float4*)&As[cur][k][ty*8];
            float4 a1 = *(const float4*)&As[cur][k][ty*8+4];
            float4 b0 = *(const float4*)&Bs[cur][k][tx*4];
            float4 b1 = *(const float4*)&Bs[cur][k][64 + tx*4];
            float av[8] = {a0.x,a0.y,a0.z,a0.w,a1.x,a1.y,a1.z,a1.w};
            float bv[8] = {b0.x,b0.y,b0.z,b0.w,b1.x,b1.y,b1.z,b1.w};
#pragma unroll
            for (int i=0;i<8;i++)
#pragma unroll
                for (int j=0;j<8;j++)
                    acc[i][j] = fmaf(av[i], bv[j], acc[i][j]);
        }
        if (t+1 < nt){
            const int nb = cur ^ 1;
#pragma unroll
            for (int u=0;u<2;u++){
                int idx = tid + u*128; int r = idx>>2, c4 = idx&3;
                As[nb][c4*4+0][r]=pa[u].x; As[nb][c4*4+1][r]=pa[u].y;
                As[nb][c4*4+2][r]=pa[u].z; As[nb][c4*4+3][r]=pa[u].w;
            }
#pragma unroll
            for (int u=0;u<4;u++){
                int idx = tid + u*128; int r = idx>>2, c4 = idx&3;
                Bs[nb][c4*4+0][r]=pw[u].x; Bs[nb][c4*4+1][r]=pw[u].y;
                Bs[nb][c4*4+2][r]=pw[u].z; Bs[nb][c4*4+3][r]=pw[u].w;
            }
            __syncthreads();
        }
    }

    float bb[8];
#pragma unroll
    for (int j=0;j<8;j++) bb[j]=0.f;
    if (bias1){
#pragma unroll
        for (int j=0;j<4;j++){ bb[j] += bias1[o0 + tx*4 + j]; bb[j+4] += bias1[o0 + 64 + tx*4 + j]; }
    }
    if (bias2){
#pragma unroll
        for (int j=0;j<4;j++){ bb[j] += bias2[o0 + tx*4 + j]; bb[j+4] += bias2[o0 + 64 + tx*4 + j]; }
    }
#pragma unroll
    for (int i=0;i<8;i++){
        float* rowp = C + (size_t)(m0 + ty*8 + i)*O + o0;
        float v[8];
#pragma unroll
        for (int j=0;j<8;j++) v[j] = acc[i][j] + bb[j];
        if (accum){
            float4 o0v = *(const float4*)(rowp + tx*4);
            float4 o1v = *(const float4*)(rowp + 64 + tx*4);
            v[0]+=o0v.x; v[1]+=o0v.y; v[2]+=o0v.z; v[3]+=o0v.w;
            v[4]+=o1v.x; v[5]+=o1v.y; v[6]+=o1v.z; v[7]+=o1v.w;
        }
        if (relu){
#pragma unroll
            for (int j=0;j<8;j++) v[j] = fmaxf(v[j], 0.f);
        }
        *(float4*)(rowp + tx*4)      = make_float4(v[0],v[1],v[2],v[3]);
        *(float4*)(rowp + 64 + tx*4) = make_float4(v[4],v[5],v[6],v[7]);
    }
}

// ---------------- fused gate GEMM -------------------------------------------
__global__ __launch_bounds__(128) void gates_gemm(
    const float* __restrict__ A1, const float* __restrict__ W1,
    const float* __restrict__ A2, const float* __restrict__ W2,
    float* __restrict__ C,
    const float* __restrict__ bias1, const float* __restrict__ bias2)
{
    const int O = 4*Hh;
    const int K = Hh;
    const int m0 = blockIdx.x * GBM;
    const int o0 = blockIdx.y * GBO;
    const int tid = threadIdx.x;
    const int ty = tid >> 4;
    const int tx = tid & 15;

    __shared__ __align__(16) float As[2][GBK][GBM];
    __shared__ __align__(16) float Bs[2][GBK][GBO];

    float acc[8][8];
#pragma unroll
    for (int i=0;i<8;i++)
#pragma unroll
        for (int j=0;j<8;j++) acc[i][j]=0.f;

    const int nt = K / GBK;

    for (int ph=0; ph<2; ph++){
        const float* A = ph ? A2 : A1;
        const float* W = ph ? W2 : W1;

#pragma unroll
        for (int u=0;u<2;u++){
            int idx = tid + u*128; int r = idx>>2, c4 = idx&3;
            float4 v = *(const float4*)(A + (size_t)(m0+r)*K + c4*4);
            As[0][c4*4+0][r]=v.x; As[0][c4*4+1][r]=v.y; As[0][c4*4+2][r]=v.z; As[0][c4*4+3][r]=v.w;
        }
#pragma unroll
        for (int u=0;u<4;u++){
            int idx = tid + u*128; int r = idx>>2, c4 = idx&3;
            float4 v = *(const float4*)(W + (size_t)(o0+r)*K + c4*4);
            Bs[0][c4*4+0][r]=v.x; Bs[0][c4*4+1][r]=v.y; Bs[0][c4*4+2][r]=v.z; Bs[0][c4*4+3][r]=v.w;
        }
        __syncthreads();

        float4 pa[2], pw[4];
        for (int t=0; t<nt; t++){
            const int cur = t & 1;
            if (t+1 < nt){
                const int kt = (t+1)*GBK;
#pragma unroll
                for (int u=0;u<2;u++){
                    int idx = tid + u*128; int r = idx>>2, c4 = idx&3;
                    pa[u] = *(const float4*)(A + (size_t)(m0+r)*K + kt + c4*4);
                }
#pragma unroll
                for (int u=0;u<4;u++){
                    int idx = tid + u*128; int r = idx>>2, c4 = idx&3;
                    pw[u] = *(const float4*)(W + (size_t)(o0+r)*K + kt + c4*4);
                }
            }
#pragma unroll
            for (int k=0;k<GBK;k++){
                float4 a0 = *(const float4*)&As[cur][k][ty*8];
                float4 a1 = *(const float4*)&As[cur][k][ty*8+4];
                float4 b0 = *(const float4*)&Bs[cur][k][tx*4];
                float4 b1 = *(const float4*)&Bs[cur][k][64 + tx*4];
                float av[8] = {a0.x,a0.y,a0.z,a0.w,a1.x,a1.y,a1.z,a1.w};
                float bv[8] = {b0.x,b0.y,b0.z,b0.w,b1.x,b1.y,b1.z,b1.w};
#pragma unroll
                for (int i=0;i<8;i++)
#pragma unroll
                    for (int j=0;j<8;j++)
                        acc[i][j] = fmaf(av[i], bv[j], acc[i][j]);
            }
            if (t+1 < nt){
                const int nb = cur ^ 1;
#pragma unroll
                for (int u=0;u<2;u++){
                    int idx = tid + u*128; int r = idx>>2, c4 = idx&3;
                    As[nb][c4*4+0][r]=pa[u].x; As[nb][c4*4+1][r]=pa[u].y;
                    As[nb][c4*4+2][r]=pa[u].z; As[nb][c4*4+3][r]=pa[u].w;
                }
#pragma unroll
                for (int u=0;u<4;u++){
                    int idx = tid + u*128; int r = idx>>2, c4 = idx&3;
                    Bs[nb][c4*4+0][r]=pw[u].x; Bs[nb][c4*4+1][r]=pw[u].y;
                    Bs[nb][c4*4+2][r]=pw[u].z; Bs[nb][c4*4+3][r]=pw[u].w;
                }
                __syncthreads();
            }
        }
        __syncthreads();
    }

    float bb[8];
#pragma unroll
    for (int j=0;j<4;j++){
        bb[j]   = bias1[o0 + tx*4 + j]      + bias2[o0 + tx*4 + j];
        bb[j+4] = bias1[o0 + 64 + tx*4 + j] + bias2[o0 + 64 + tx*4 + j];
    }
#pragma unroll
    for (int i=0;i<8;i++){
        float* rowp = C + (size_t)(m0 + ty*8 + i)*O + o0;
        *(float4*)(rowp + tx*4)      = make_float4(acc[i][0]+bb[0], acc[i][1]+bb[1], acc[i][2]+bb[2], acc[i][3]+bb[3]);
        *(float4*)(rowp + 64 + tx*4) = make_float4(acc[i][4]+bb[4], acc[i][5]+bb[5], acc[i][6]+bb[6], acc[i][7]+bb[7]);
    }
}

// ---------------- LayerNorm -------------------------------------------------
__global__ void ln_kernel(const float* __restrict__ in, float* __restrict__ out,
                          const float* __restrict__ gamma, const float* __restrict__ beta)
{
    size_t row = blockIdx.x;
    int t = threadIdx.x;
    float v = in[row*Hh + t];
    float s = v;
#pragma unroll
    for (int o=16;o>0;o>>=1) s += __shfl_xor_sync(0xffffffffu, s, o);
    __shared__ float sm[4], sv[4];
    int w = t>>5, l = t&31;
    if (l==0) sm[w] = s;
    __syncthreads();
    float mu = (sm[0]+sm[1]+sm[2]+sm[3]) * (1.0f/Hh);
    float xc = v - mu;
    float q = xc*xc;
#pragma unroll
    for (int o=16;o>0;o>>=1) q += __shfl_xor_sync(0xffffffffu, q, o);
    if (l==0) sv[w] = q;
    __syncthreads();
    float var = (sv[0]+sv[1]+sv[2]+sv[3]) * (1.0f/Hh);
    out[row*Hh + t] = xc * rsqrtf(var + LNEPS) * gamma[t] + beta[t];
}

// ---------------- fused LSTM + LayerNorm ------------------------------------
__global__ void lstm_ln(const float* __restrict__ gates,
                        float* __restrict__ c, float* __restrict__ h,
                        float* __restrict__ e,
                        const float* __restrict__ gamma, const float* __restrict__ beta)
{
    size_t row = blockIdx.x;
    int t = threadIdx.x;
    const float* g = gates + row*(4*Hh);
    size_t idx = row*Hh + t;

    float iv = sigf(g[t]);
    float fv = sigf(g[Hh + t]);
    float gv = tanhf(g[2*Hh + t]);
    float ov = sigf(g[3*Hh + t]);
    float cn = fv*c[idx] + iv*gv;
    c[idx] = cn;
    float hv = ov*tanhf(cn);
    h[idx] = hv;

    float s = hv;
#pragma unroll
    for (int o=16;o>0;o>>=1) s += __shfl_xor_sync(0xffffffffu, s, o);
    __shared__ float sm[4], sv[4];
    int w = t>>5, l = t&31;
    if (l==0) sm[w] = s;
    __syncthreads();
    float mu = (sm[0]+sm[1]+sm[2]+sm[3]) * (1.0f/Hh);
    float xc = hv - mu;
    float q = xc*xc;
#pragma unroll
    for (int o=16;o>0;o>>=1) q += __shfl_xor_sync(0xffffffffu, q, o);
    if (l==0) sv[w] = q;
    __syncthreads();
    float var = (sv[0]+sv[1]+sv[2]+sv[3]) * (1.0f/Hh);
    e[idx] = xc * rsqrtf(var + LNEPS) * gamma[t] + beta[t];
}

// ---------------- init MLP ---------------------------------------------------
__global__ void init_mlp(const float* __restrict__ kk, const float* __restrict__ nn,
    const float* __restrict__ w1, const float* __restrict__ b1,
    const float* __restrict__ w2, const float* __restrict__ b2,
    const float* __restrict__ w3, const float* __restrict__ b3,
    float* __restrict__ out)
{
    int b = blockIdx.x, t = threadIdx.x;
    __shared__ float s0[Hh], s1[Hh];
    float a = w1[t*2+0]*kk[b] + w1[t*2+1]*nn[b] + b1[t];
    s0[t] = fmaxf(a, 0.f);
    __syncthreads();
    a = b2[t];
    for (int q=0;q<Hh;q++) a = fmaf(w2[t*Hh+q], s0[q], a);
    s1[t] = fmaxf(a, 0.f);
    __syncthreads();
    a = b3[t];
    for (int q=0;q<Hh;q++) a = fmaf(w3[t*Hh+q], s1[q], a);
    out[b*Hh + t] = a;
}

// ---------------- msg MLP iteration-0 fast path ------------------------------
__global__ void m0_mlp(const float* __restrict__ embed,
    const float* __restrict__ w1, const float* __restrict__ b1,
    const float* __restrict__ w2, const float* __restrict__ b2,
    const float* __restrict__ w3, const float* __restrict__ b3,
    float* __restrict__ out)
{
    int b = blockIdx.x, t = threadIdx.x;
    __shared__ float s0[Hh], s1[Hh];
    s0[t] = embed[(size_t)b*Nn*Hh + t];
    __syncthreads();
    float a = b1[t];
    for (int q=0;q<Hh;q++) a = fmaf(w1[t*Hh+q], s0[q], a);
    s1[t] = fmaxf(a, 0.f);
    __syncthreads();
    a = b2[t];
    for (int q=0;q<Hh;q++) a = fmaf(w2[t*Hh+q], s1[q], a);
    __syncthreads();
    s0[t] = fmaxf(a, 0.f);
    __syncthreads();
    a = b3[t];
    for (int q=0;q<Hh;q++) a = fmaf(w3[t*Hh+q], s0[q], a);
    out[b*Hh + t] = a;
}

// ---------------- row sums of x (once) ---------------------------------------
__global__ void rowsum_kernel(const float* __restrict__ x, float* __restrict__ rs)
{
    size_t row = blockIdx.x;
    const float4* p = (const float4*)(x + row*(size_t)Nn);
    float s = 0.f;
    for (int j=threadIdx.x; j<Nn/4; j+=128){
        float4 v = p[j];
        s += (v.x+v.y)+(v.z+v.w);
    }
#pragma unroll
    for (int o=16;o>0;o>>=1) s += __shfl_xor_sync(0xffffffffu, s, o);
    __shared__ float sm[4];
    int w = threadIdx.x>>5, l = threadIdx.x&31;
    if (l==0) sm[w] = s;
    __syncthreads();
    if (threadIdx.x==0) rs[row] = (sm[0]+sm[1])+(sm[2]+sm[3]);
}

__global__ void bcast_init(const float* __restrict__ i0, float* __restrict__ h, float* __restrict__ c)
{
    size_t idx = (size_t)blockIdx.x*blockDim.x + threadIdx.x;
    int b  = (int)(idx / ((size_t)Nn*Hh));
    int hh = (int)(idx % Hh);
    h[idx] = i0[b*Hh + hh];
    c[idx] = 0.f;
}

__global__ void outer_msg(const float* __restrict__ rs, const float* __restrict__ m0,
                          float* __restrict__ msg)
{
    size_t idx = (size_t)blockIdx.x*blockDim.x + threadIdx.x;
    int b  = (int)(idx / ((size_t)Nn*Hh));
    size_t row = idx / Hh;
    int hh = (int)(idx % Hh);
    msg[idx] = rs[row] * m0[b*Hh + hh];
}

// ---------------- vote -------------------------------------------------------
__global__ void vote_part(const float* __restrict__ v2, const float* __restrict__ w3,
                          const float* __restrict__ b3v, const float* __restrict__ mask,
                          float* __restrict__ part)
{
    int b = blockIdx.y;
    int blk = blockIdx.x;
    int tid = threadIdx.x;
    int w = tid>>5, l = tid&31;
    __shared__ float sw[Hh];
    if (tid < Hh) sw[tid] = w3[tid];
    __syncthreads();
    float s = 0.f;
    for (int i = blk*8 + w; i < Nn; i += 64){
        const float* rp = v2 + ((size_t)b*Nn + i)*Hh;
        float d = 0.f;
#pragma unroll
        for (int q=0;q<4;q++) d = fmaf(rp[l + 32*q], sw[l + 32*q], d);
#pragma unroll
        for (int o=16;o>0;o>>=1) d += __shfl_xor_sync(0xffffffffu, d, o);
        s += (d + b3v[0]) * mask[(size_t)b*Nn + i];
    }
    __shared__ float wsum[8];
    if (l==0) wsum[w] = s;
    __syncthreads();
    if (tid==0){
        float t = 0.f;
        for (int q=0;q<8;q++) t += wsum[q];
        part[b*8 + blk] = t;
    }
}

__global__ void vote_final(const float* __restrict__ part, float* __restrict__ out)
{
    int b = threadIdx.x;
    if (b < Bz){
        float s = 0.f;
        for (int q=0;q<8;q++) s += part[b*8+q];
        out[b] = 1.f/(1.f+expf(-s));
    }
}

// =============================================================================
extern "C" void kernel_launch(void* const* d_in, const int* in_sizes, int n_in,
                              void* d_out, int out_size)
{
    const float* x    = (const float*)d_in[0];
    const float* kv   = (const float*)d_in[1];
    const float* nv   = (const float*)d_in[2];
    const float* mask = (const float*)d_in[3];
    const float* iw1  = (const float*)d_in[4];
    const float* ib1  = (const float*)d_in[5];
    const float* iw2  = (const float*)d_in[6];
    const float* ib2  = (const float*)d_in[7];
    const float* iw3  = (const float*)d_in[8];
    const float* ib3  = (const float*)d_in[9];
    const float* mw1  = (const float*)d_in[10];
    const float* mb1  = (const float*)d_in[11];
    const float* mw2  = (const float*)d_in[12];
    const float* mb2  = (const float*)d_in[13];
    const float* mw3  = (const float*)d_in[14];
    const float* mb3  = (const float*)d_in[15];
    const float* wih  = (const float*)d_in[16];
    const float* whh  = (const float*)d_in[17];
    const float* bih  = (const float*)d_in[18];
    const float* bhh  = (const float*)d_in[19];
    const float* lng  = (const float*)d_in[20];
    const float* lnb  = (const float*)d_in[21];
    const float* vw1  = (const float*)d_in[22];
    const float* vb1  = (const float*)d_in[23];
    const float* vw2  = (const float*)d_in[24];
    const float* vb2  = (const float*)d_in[25];
    const float* vw3  = (const float*)d_in[26];
    const float* vb3  = (const float*)d_in[27];
    float* out = (float*)d_out;

    float *p_h,*p_c,*p_e,*p_t1,*p_t2,*p_m,*p_msg,*p_g,*p_rs,*p_i0,*p_m0,*p_vp;
    __nv_bfloat16 *p_xh,*p_xl,*p_mTh,*p_mTl;
    cudaGetSymbolAddress((void**)&p_h,   g_h);
    cudaGetSymbolAddress((void**)&p_c,   g_c);
    cudaGetSymbolAddress((void**)&p_e,   g_e);
    cudaGetSymbolAddress((void**)&p_t1,  g_t1);
    cudaGetSymbolAddress((void**)&p_t2,  g_t2);
    cudaGetSymbolAddress((void**)&p_m,   g_m);
    cudaGetSymbolAddress((void**)&p_msg, g_msg);
    cudaGetSymbolAddress((void**)&p_g,   g_gates);
    cudaGetSymbolAddress((void**)&p_rs,  g_rs);
    cudaGetSymbolAddress((void**)&p_i0,  g_i0);
    cudaGetSymbolAddress((void**)&p_m0,  g_m0);
    cudaGetSymbolAddress((void**)&p_vp,  g_vp);
    cudaGetSymbolAddress((void**)&p_xh,  g_xh);
    cudaGetSymbolAddress((void**)&p_xl,  g_xl);
    cudaGetSymbolAddress((void**)&p_mTh, g_mTh);
    cudaGetSymbolAddress((void**)&p_mTl, g_mTl);

    cudaFuncSetAttribute(agg_mma, cudaFuncAttributeMaxDynamicSharedMemorySize, AGG_SMEM);

    const int BN = Bz*Nn;
    const int ELEM_BLOCKS = (BN*Hh)/256;

    // ---- init ----
    init_mlp<<<Bz, Hh>>>(kv, nv, iw1, ib1, iw2, ib2, iw3, ib3, p_i0);
    rowsum_kernel<<<BN, 128>>>(x, p_rs);
    conv_x<<<(Bz*Nn*Nn)/(4*256), 256>>>((const float4*)x, p_xh, p_xl);
    bcast_init<<<ELEM_BLOCKS, 256>>>(p_i0, p_h, p_c);
    ln_kernel<<<BN, Hh>>>(p_h, p_e, lng, lnb);

    // ---- iteration 0 (h broadcast => msg = rowsum outer m0) ----
    m0_mlp<<<Bz, Hh>>>(p_e, mw1, mb1, mw2, mb2, mw3, mb3, p_m0);
    outer_msg<<<ELEM_BLOCKS, 256>>>(p_rs, p_m0, p_msg);
    gates_gemm<<<dim3(BN/GBM, (4*Hh)/GBO), 128>>>(p_msg, wih, p_h, whh, p_g, bih, bhh);
    lstm_ln<<<BN, Hh>>>(p_g, p_c, p_h, p_e, lng, lnb);

    // ---- iterations 1..7 ----
    for (int it = 1; it < NITERS; it++){
        gemm_nt<<<dim3(BN/GBM, 1, 1), 128>>>(p_e,  mw1, p_t1, BN, Hh, Hh, 0,0,0, mb1, nullptr, 1, 0);
        gemm_nt<<<dim3(BN/GBM, 1, 1), 128>>>(p_t1, mw2, p_t2, BN, Hh, Hh, 0,0,0, mb2, nullptr, 1, 0);
        gemm_nt<<<dim3(BN/GBM, 1, 1), 128>>>(p_t2, mw3, p_m,  BN, Hh, Hh, 0,0,0, mb3, nullptr, 0, 0);
        transpose_conv<<<dim3(Nn/32, Hh/32, Bz), dim3(32, 8)>>>(p_m, p_mTh, p_mTl);
        agg_mma<<<dim3(Nn/128, 1, Bz), 256, AGG_SMEM>>>(p_xh, p_xl, p_mTh, p_mTl, p_msg);
        gates_gemm<<<dim3(BN/GBM, (4*Hh)/GBO), 128>>>(p_msg, wih, p_h, whh, p_g, bih, bhh);
        lstm_ln<<<BN, Hh>>>(p_g, p_c, p_h, p_e, lng, lnb);
    }

    // ---- vote ----
    gemm_nt<<<dim3(BN/GBM, 1, 1), 128>>>(p_e,  vw1, p_t1, BN, Hh, Hh, 0,0,0, vb1, nullptr, 1, 0);
    gemm_nt<<<dim3(BN/GBM, 1, 1), 128>>>(p_t1, vw2, p_t2, BN, Hh, Hh, 0,0,0, vb2, nullptr, 1, 0);
    vote_part<<<dim3(8, Bz), 256>>>(p_t2, vw3, vb3, mask, p_vp);
    vote_final<<<1, 32>>>(p_vp, out);
}